// round 1
// baseline (speedup 1.0000x reference)
#include <cuda_runtime.h>
#include <cstdint>

// Problem constants (fixed by the dataset)
#define B_    2
#define N_    16384
#define M_    16384
#define K_    32
#define CIN   64
#define COUT  128
#define KS_   15
#define JC    (KS_ * CIN)       // 960
#define QT    32                // queries per CTA
#define NTHREADS 256
#define SH_STRIDE 34            // [jc][q] row stride (floats): even -> 8B aligned q-pairs

// ---- packed f32x2 helpers (FFMA2 only reachable via PTX) ----
__device__ __forceinline__ unsigned long long pack2(float lo, float hi) {
    unsigned long long r;
    asm("mov.b64 %0, {%1, %2};" : "=l"(r) : "f"(lo), "f"(hi));
    return r;
}
__device__ __forceinline__ void fma2(unsigned long long& d,
                                     unsigned long long a,
                                     unsigned long long b) {
    asm("fma.rn.f32x2 %0, %1, %2, %3;" : "=l"(d) : "l"(a), "l"(b), "l"(d));
}
__device__ __forceinline__ float2 unpack2(unsigned long long v) {
    float2 f;
    asm("mov.b64 {%0, %1}, %2;" : "=f"(f.x), "=f"(f.y) : "l"(v));
    return f;
}

extern __shared__ float smem[];

__global__ __launch_bounds__(NTHREADS, 1)
void kpconv_kernel(const float* __restrict__ qp,    // [B,N,3]
                   const float* __restrict__ sp,    // [B,M,3]
                   const float* __restrict__ sf,    // [B,M,CIN]
                   const int*   __restrict__ nidx,  // [B,N,K]
                   const float* __restrict__ kp,    // [KS,3]
                   const float* __restrict__ W,     // [KS,CIN,COUT]
                   const float* __restrict__ bias,  // [COUT]
                   float*       __restrict__ out)   // [B,N,COUT]
{
    // ---- smem carve ----
    float* s_h    = smem;                                  // [JC][SH_STRIDE]
    float* s_infl = s_h + JC * SH_STRIDE;                  // [QT][K][KS]
    int*   s_idx  = (int*)(s_infl + QT * K_ * KS_);        // [QT][K]
    float* s_qp   = (float*)(s_idx + QT * K_);             // [QT][3]
    float* s_kp   = s_qp + QT * 3;                         // [KS][3]

    const int tid = threadIdx.x;
    const int b   = blockIdx.x >> 9;            // N_/QT = 512 tiles per batch
    const int q0  = (blockIdx.x & 511) * QT;

    if (tid < KS_ * 3) s_kp[tid] = kp[tid];
    if (tid < QT * 3)  s_qp[tid] = qp[(size_t)(b * N_ + q0) * 3 + tid];
    __syncthreads();

    // ================= Stage A: influences [QT][K][KS] =================
    #pragma unroll
    for (int t = 0; t < (QT * K_) / NTHREADS; ++t) {
        const int pi = tid + t * NTHREADS;
        const int q  = pi >> 5;
        const int k  = pi & 31;
        const int idx = nidx[((size_t)(b * N_ + q0 + q)) * K_ + k];
        s_idx[q * K_ + k] = idx;
        const float* p = sp + (size_t)(b * M_ + idx) * 3;
        const float rx = p[0] - s_qp[q * 3 + 0];
        const float ry = p[1] - s_qp[q * 3 + 1];
        const float rz = p[2] - s_qp[q * 3 + 2];
        float e[KS_];
        float sum = 0.f;
        #pragma unroll
        for (int j = 0; j < KS_; ++j) {
            const float dx = rx - s_kp[j * 3 + 0];
            const float dy = ry - s_kp[j * 3 + 1];
            const float dz = rz - s_kp[j * 3 + 2];
            const float d2 = dx * dx + dy * dy + dz * dz;
            // sigma = 0.05 -> 1/(2*sigma^2) = 200
            e[j] = __expf(-200.0f * d2);
            sum += e[j];
        }
        const float inv = 1.0f / (sum + 1e-6f);
        #pragma unroll
        for (int j = 0; j < KS_; ++j)
            s_infl[(q * K_ + k) * KS_ + j] = e[j] * inv;
    }
    __syncthreads();

    // ====== Stage B: h[jc][q] = sum_k infl[q][k][j] * feat[k][c] ======
    {
        const int wid  = tid >> 5;
        const int lane = tid & 31;
        #pragma unroll
        for (int qi = 0; qi < QT / 8; ++qi) {       // 4 queries per warp
            const int q = wid * (QT / 8) + qi;
            unsigned long long hacc[KS_];
            #pragma unroll
            for (int j = 0; j < KS_; ++j) hacc[j] = 0ull;

            const float* iprow = s_infl + (q * K_) * KS_;
            #pragma unroll 4
            for (int k = 0; k < K_; ++k) {
                const int idx = s_idx[q * K_ + k];
                // two consecutive channels per lane: c = 2*lane, 2*lane+1 (8B aligned)
                const unsigned long long f2 =
                    *(const unsigned long long*)(sf + (size_t)(b * M_ + idx) * CIN + 2 * lane);
                const float* ip = iprow + k * KS_;
                #pragma unroll
                for (int j = 0; j < KS_; ++j) {
                    const float w = ip[j];               // smem broadcast
                    fma2(hacc[j], f2, pack2(w, w));
                }
            }
            #pragma unroll
            for (int j = 0; j < KS_; ++j) {
                const float2 v = unpack2(hacc[j]);
                s_h[(size_t)(j * CIN + 2 * lane)     * SH_STRIDE + q] = v.x;
                s_h[(size_t)(j * CIN + 2 * lane + 1) * SH_STRIDE + q] = v.y;
            }
        }
    }
    __syncthreads();

    // ====== Stage C: out[q][o] = bias[o] + sum_jc h[jc][q] * W[jc][o] ======
    {
        const int o     = tid & 127;
        const int qbase = (tid >> 7) * (QT / 2);    // 0 or 16
        const float bv  = bias[o];
        const unsigned long long binit = pack2(bv, bv);
        unsigned long long acc[QT / 4];             // 8 packed q-pairs
        #pragma unroll
        for (int p = 0; p < QT / 4; ++p) acc[p] = binit;

        const float* wp = W + o;
        const float* hp = s_h + qbase;
        #pragma unroll 4
        for (int jc = 0; jc < JC; ++jc) {
            const float w = wp[(size_t)jc * COUT];  // coalesced, L2-resident
            const unsigned long long ww = pack2(w, w);
            const unsigned long long* h2 =
                (const unsigned long long*)(hp + (size_t)jc * SH_STRIDE);
            #pragma unroll
            for (int p = 0; p < QT / 4; ++p) fma2(acc[p], h2[p], ww);
        }

        float* op = out + ((size_t)(b * N_ + q0 + qbase)) * COUT + o;
        #pragma unroll
        for (int p = 0; p < QT / 4; ++p) {
            const float2 v = unpack2(acc[p]);
            op[(size_t)(2 * p + 0) * COUT] = v.x;
            op[(size_t)(2 * p + 1) * COUT] = v.y;
        }
    }
}

extern "C" void kernel_launch(void* const* d_in, const int* in_sizes, int n_in,
                              void* d_out, int out_size) {
    const float* qp   = (const float*)d_in[0];
    const float* sp   = (const float*)d_in[1];
    const float* sf   = (const float*)d_in[2];
    const int*   nidx = (const int*)  d_in[3];
    const float* kp   = (const float*)d_in[4];
    const float* W    = (const float*)d_in[5];
    const float* bias = (const float*)d_in[6];
    float* out = (float*)d_out;

    const int smem_bytes =
        (JC * SH_STRIDE + QT * K_ * KS_ + QT * 3 + KS_ * 3) * (int)sizeof(float)
        + QT * K_ * (int)sizeof(int);

    static bool attr_set = false;
    if (!attr_set) {
        cudaFuncSetAttribute(kpconv_kernel,
                             cudaFuncAttributeMaxDynamicSharedMemorySize,
                             smem_bytes);
        attr_set = true;
    }

    const int grid = B_ * (N_ / QT);   // 1024 CTAs
    kpconv_kernel<<<grid, NTHREADS, smem_bytes>>>(qp, sp, sf, nidx, kp, W, bias, out);
}

// round 2
// speedup vs baseline: 1.6676x; 1.6676x over previous
#include <cuda_runtime.h>
#include <cstdint>

#define B_    2
#define N_    16384
#define M_    16384
#define K_    32
#define CIN   64
#define COUT  128
#define KS_   15
#define JC    (KS_ * CIN)        // 960
#define JCH   (JC / 2)           // 480 per jc-half
#define QT    16                 // queries per CTA
#define NTHREADS 256
#define HSTRIDE 18               // s_h row stride in floats (even -> 8B aligned q-pairs)
#define ISTRIDE 17               // per-k influence stride in ull (bank-spread)

typedef unsigned long long ull;

__device__ __forceinline__ ull pack2(float lo, float hi) {
    ull r;
    asm("mov.b64 %0, {%1, %2};" : "=l"(r) : "f"(lo), "f"(hi));
    return r;
}
__device__ __forceinline__ void fma2(ull& d, ull a, ull b) {
    asm("fma.rn.f32x2 %0, %1, %2, %3;" : "=l"(d) : "l"(a), "l"(b), "l"(d));
}
__device__ __forceinline__ float2 unpack2(ull v) {
    float2 f;
    asm("mov.b64 {%0, %1}, %2;" : "=f"(f.x), "=f"(f.y) : "l"(v));
    return f;
}

extern __shared__ float smem[];

// smem plan (floats):
//   s_h     : [JC][HSTRIDE]                 = 17280 f   (69.1 KB)
//   s_stage : [8 warps][K_][ISTRIDE] ull    =  8704 f   (34.8 KB)  (reused for reduction)
//   s_idx   : [QT][K_] int                  =   512 f
//   s_qp    : [QT][3]                       =    48 f
//   s_kp    : [KS_][3]                      =    45 f
// total ~106.4 KB -> 2 CTAs/SM

__global__ __launch_bounds__(NTHREADS, 2)
void kpconv_kernel(const float* __restrict__ qp,
                   const float* __restrict__ sp,
                   const float* __restrict__ sf,
                   const int*   __restrict__ nidx,
                   const float* __restrict__ kp,
                   const float* __restrict__ W,
                   const float* __restrict__ bias,
                   float*       __restrict__ out)
{
    float* s_h     = smem;                               // 17280 f
    ull*   s_stage = (ull*)(smem + JC * HSTRIDE);        // 4352 ull
    int*   s_idx   = (int*)(s_stage + 8 * K_ * ISTRIDE); // 512 int
    float* s_qp    = (float*)(s_idx + QT * K_);          // 48 f
    float* s_kp    = s_qp + QT * 3;                      // 45 f

    const int tid  = threadIdx.x;
    const int b    = blockIdx.x >> 10;                   // 1024 tiles per batch
    const int q0   = (blockIdx.x & 1023) * QT;
    const int wid  = tid >> 5;
    const int lane = tid & 31;

    if (tid < KS_ * 3) s_kp[tid] = kp[tid];
    if (tid < QT * 3)  s_qp[tid] = qp[(size_t)(b * N_ + q0) * 3 + tid];
    __syncthreads();

    // ============ fused Stage A (influences) + Stage B (aggregate h) ============
    ull* stg = s_stage + (size_t)wid * K_ * ISTRIDE;

    #pragma unroll
    for (int qq = 0; qq < 2; ++qq) {
        const int q = wid * 2 + qq;

        // --- Stage A: lane = neighbor k ---
        {
            const int k   = lane;
            const int idx = nidx[((size_t)(b * N_ + q0 + q)) * K_ + k];
            s_idx[q * K_ + k] = idx;
            const float* p = sp + (size_t)(b * M_ + idx) * 3;
            const float rx = p[0] - s_qp[q * 3 + 0];
            const float ry = p[1] - s_qp[q * 3 + 1];
            const float rz = p[2] - s_qp[q * 3 + 2];
            float e[KS_];
            float sum = 0.f;
            #pragma unroll
            for (int j = 0; j < KS_; ++j) {
                const float dx = rx - s_kp[j * 3 + 0];
                const float dy = ry - s_kp[j * 3 + 1];
                const float dz = rz - s_kp[j * 3 + 2];
                const float d2 = dx * dx + dy * dy + dz * dz;
                e[j] = __expf(-200.0f * d2);   // sigma = 0.05
                sum += e[j];
            }
            const float inv = 1.0f / (sum + 1e-6f);
            #pragma unroll
            for (int j = 0; j < KS_; ++j) {
                const float v = e[j] * inv;
                stg[k * ISTRIDE + j] = pack2(v, v);   // pre-duplicated
            }
        }
        __syncwarp();

        // --- Stage B: lane = channel pair (c = 2*lane, 2*lane+1) ---
        {
            ull hacc[KS_];
            #pragma unroll
            for (int j = 0; j < KS_; ++j) hacc[j] = 0ull;

            const int* iq = s_idx + q * K_;
            #pragma unroll 4
            for (int k = 0; k < K_; ++k) {
                const int idx = iq[k];
                const ull f2 =
                    *(const ull*)(sf + (size_t)(b * M_ + idx) * CIN + 2 * lane);
                const ull* ip = stg + k * ISTRIDE;
                #pragma unroll
                for (int j = 0; j < KS_; ++j)
                    fma2(hacc[j], f2, ip[j]);
            }
            // transpose-store into s_h[jc][q]
            #pragma unroll
            for (int j = 0; j < KS_; ++j) {
                const float2 v = unpack2(hacc[j]);
                s_h[(j * CIN + 2 * lane)     * HSTRIDE + q] = v.x;
                s_h[(j * CIN + 2 * lane + 1) * HSTRIDE + q] = v.y;
            }
        }
        __syncwarp();   // s_stage reused next qq
    }
    __syncthreads();

    // ============ Stage C: out[q][o] = bias[o] + sum_jc h[jc][q]*W[jc][o] ======
    // thread tile: 4 consecutive o x 4 consecutive q, split jc range in half
    const int half  = tid >> 7;       // 0/1 -> jc half
    const int r     = tid & 127;
    const int otile = r & 31;         // o = otile*4 .. +3
    const int qg    = r >> 5;         // q = qg*4 .. +3
    const int jc0   = half * JCH;

    ull acc[4][2];
    #pragma unroll
    for (int oo = 0; oo < 4; ++oo) { acc[oo][0] = 0ull; acc[oo][1] = 0ull; }

    const float* wp = W + (size_t)jc0 * COUT + otile * 4;
    const float* hp = s_h + jc0 * HSTRIDE + qg * 4;

    #pragma unroll 4
    for (int jc = 0; jc < JCH; ++jc) {
        const float4 w4 = *(const float4*)(wp + (size_t)jc * COUT);
        const ull h0 = *(const ull*)(hp + jc * HSTRIDE);
        const ull h1 = *(const ull*)(hp + jc * HSTRIDE + 2);
        const ull wx = pack2(w4.x, w4.x);
        const ull wy = pack2(w4.y, w4.y);
        const ull wz = pack2(w4.z, w4.z);
        const ull ww = pack2(w4.w, w4.w);
        fma2(acc[0][0], h0, wx); fma2(acc[0][1], h1, wx);
        fma2(acc[1][0], h0, wy); fma2(acc[1][1], h1, wy);
        fma2(acc[2][0], h0, wz); fma2(acc[2][1], h1, wz);
        fma2(acc[3][0], h0, ww); fma2(acc[3][1], h1, ww);
    }

    __syncthreads();
    ull* s_red = s_stage;   // reuse: 128 threads x 8 ull = 8 KB
    if (half == 1) {
        #pragma unroll
        for (int oo = 0; oo < 4; ++oo) {
            s_red[r * 8 + oo * 2 + 0] = acc[oo][0];
            s_red[r * 8 + oo * 2 + 1] = acc[oo][1];
        }
    }
    __syncthreads();
    if (half == 0) {
        const float4 b4 = *(const float4*)(bias + otile * 4);
        float v[4][4];   // [oo][qq]
        #pragma unroll
        for (int oo = 0; oo < 4; ++oo) {
            #pragma unroll
            for (int p = 0; p < 2; ++p) {
                ull a = acc[oo][p];
                const ull other = s_red[r * 8 + oo * 2 + p];
                const float2 f0 = unpack2(a);
                const float2 f1 = unpack2(other);
                v[oo][2 * p + 0] = f0.x + f1.x;
                v[oo][2 * p + 1] = f0.y + f1.y;
            }
        }
        #pragma unroll
        for (int qq = 0; qq < 4; ++qq) {
            float4 o4;
            o4.x = v[0][qq] + b4.x;
            o4.y = v[1][qq] + b4.y;
            o4.z = v[2][qq] + b4.z;
            o4.w = v[3][qq] + b4.w;
            *(float4*)(out + ((size_t)(b * N_ + q0 + qg * 4 + qq)) * COUT
                           + otile * 4) = o4;
        }
    }
}

extern "C" void kernel_launch(void* const* d_in, const int* in_sizes, int n_in,
                              void* d_out, int out_size) {
    const float* qp   = (const float*)d_in[0];
    const float* sp   = (const float*)d_in[1];
    const float* sf   = (const float*)d_in[2];
    const int*   nidx = (const int*)  d_in[3];
    const float* kp   = (const float*)d_in[4];
    const float* W    = (const float*)d_in[5];
    const float* bias = (const float*)d_in[6];
    float* out = (float*)d_out;

    const int smem_bytes =
        (JC * HSTRIDE) * (int)sizeof(float)
        + 8 * K_ * ISTRIDE * (int)sizeof(ull)
        + QT * K_ * (int)sizeof(int)
        + (QT * 3 + KS_ * 3) * (int)sizeof(float);

    static bool attr_set = false;
    if (!attr_set) {
        cudaFuncSetAttribute(kpconv_kernel,
                             cudaFuncAttributeMaxDynamicSharedMemorySize,
                             smem_bytes);
        attr_set = true;
    }

    const int grid = B_ * (N_ / QT);   // 2048 CTAs
    kpconv_kernel<<<grid, NTHREADS, smem_bytes>>>(qp, sp, sf, nidx, kp, W, bias, out);
}

// round 3
// speedup vs baseline: 1.7815x; 1.0683x over previous
#include <cuda_runtime.h>
#include <cstdint>

#define B_    2
#define N_    16384
#define M_    16384
#define K_    32
#define CIN   64
#define COUT  128
#define KS_   15
#define JC    960
#define QT    16
#define NTHREADS 256
#define HSTR  20       // s_h row stride (floats): 80B rows -> 16B aligned, 4-way store conflicts
#define ISTR  20       // s_infl per-k stride (floats): 16B aligned float4 reads
#define RSTR  18       // reduction row stride (floats): 8B aligned, low-conflict
#define SPLITS 8
#define JCS   (JC / SPLITS)   // 120 jc per warp

typedef unsigned long long ull;

__device__ __forceinline__ ull pack2(float lo, float hi) {
    ull r;
    asm("mov.b64 %0, {%1, %2};" : "=l"(r) : "f"(lo), "f"(hi));
    return r;
}
__device__ __forceinline__ void fma2(ull& d, ull a, ull b) {
    asm("fma.rn.f32x2 %0, %1, %2, %3;" : "=l"(d) : "l"(a), "l"(b), "l"(d));
}
__device__ __forceinline__ float2 unpack2(ull v) {
    float2 f;
    asm("mov.b64 {%0, %1}, %2;" : "=f"(f.x), "=f"(f.y) : "l"(v));
    return f;
}

extern __shared__ float smem[];

// smem plan (floats):
//   s_h    : [JC][HSTR]            = 19200 f (76.8 KB)  -- reused as s_red [8][128][RSTR]
//   s_infl : [8 warps][K_][ISTR]   =  5120 f (20.5 KB)
//   s_qp   : [QT][3], s_kp : [KS_][3]
// total ~98 KB -> 2 CTAs/SM

__global__ __launch_bounds__(NTHREADS, 2)
void kpconv_kernel(const float* __restrict__ qp,
                   const float* __restrict__ sp,
                   const float* __restrict__ sf,
                   const int*   __restrict__ nidx,
                   const float* __restrict__ kp,
                   const float* __restrict__ W,
                   const float* __restrict__ bias,
                   float*       __restrict__ out)
{
    float* s_h    = smem;                       // 19200 f
    float* s_infl = smem + JC * HSTR;           // 5120 f
    float* s_qp   = s_infl + SPLITS * K_ * ISTR;
    float* s_kp   = s_qp + QT * 3;

    const int tid  = threadIdx.x;
    const int b    = blockIdx.x >> 10;
    const int q0   = (blockIdx.x & 1023) * QT;
    const int wid  = tid >> 5;
    const int lane = tid & 31;

    if (tid < KS_ * 3) s_kp[tid] = kp[tid];
    if (tid < QT * 3)  s_qp[tid] = qp[(size_t)(b * N_ + q0) * 3 + tid];
    __syncthreads();

    // ============ fused Stage A (influences) + Stage B (aggregate h) ============
    float* stg = s_infl + wid * (K_ * ISTR);

    #pragma unroll
    for (int qq = 0; qq < 2; ++qq) {
        const int q = wid * 2 + qq;

        // --- Stage A: lane = neighbor k ---
        const int my_idx = nidx[((size_t)(b * N_ + q0 + q)) * K_ + lane];
        {
            const float* p = sp + (size_t)(b * M_ + my_idx) * 3;
            const float rx = p[0] - s_qp[q * 3 + 0];
            const float ry = p[1] - s_qp[q * 3 + 1];
            const float rz = p[2] - s_qp[q * 3 + 2];
            float e[KS_];
            float sum = 0.f;
            #pragma unroll
            for (int j = 0; j < KS_; ++j) {
                const float dx = rx - s_kp[j * 3 + 0];
                const float dy = ry - s_kp[j * 3 + 1];
                const float dz = rz - s_kp[j * 3 + 2];
                const float d2 = dx * dx + dy * dy + dz * dz;
                e[j] = __expf(-200.0f * d2);    // sigma = 0.05
                sum += e[j];
            }
            const float inv = 1.0f / (sum + 1e-6f);
            #pragma unroll
            for (int j = 0; j < KS_; ++j)
                stg[lane * ISTR + j] = e[j] * inv;
            stg[lane * ISTR + 15] = 0.0f;       // pad element for float4 read
        }
        __syncwarp();

        // --- Stage B: lane = channel pair (c = 2*lane, 2*lane+1) ---
        {
            ull hacc[KS_];
            #pragma unroll
            for (int j = 0; j < KS_; ++j) hacc[j] = 0ull;

            const float* sfb = sf + (size_t)b * M_ * CIN + 2 * lane;

            #pragma unroll 2
            for (int k = 0; k < K_; ++k) {
                const int idx = __shfl_sync(0xffffffffu, my_idx, k);
                const ull f2 = *(const ull*)(sfb + (size_t)idx * CIN);
                const float4* ip = (const float4*)(stg + k * ISTR);
                const float4 v0 = ip[0];
                const float4 v1 = ip[1];
                const float4 v2 = ip[2];
                const float4 v3 = ip[3];
                fma2(hacc[0],  f2, pack2(v0.x, v0.x));
                fma2(hacc[1],  f2, pack2(v0.y, v0.y));
                fma2(hacc[2],  f2, pack2(v0.z, v0.z));
                fma2(hacc[3],  f2, pack2(v0.w, v0.w));
                fma2(hacc[4],  f2, pack2(v1.x, v1.x));
                fma2(hacc[5],  f2, pack2(v1.y, v1.y));
                fma2(hacc[6],  f2, pack2(v1.z, v1.z));
                fma2(hacc[7],  f2, pack2(v1.w, v1.w));
                fma2(hacc[8],  f2, pack2(v2.x, v2.x));
                fma2(hacc[9],  f2, pack2(v2.y, v2.y));
                fma2(hacc[10], f2, pack2(v2.z, v2.z));
                fma2(hacc[11], f2, pack2(v2.w, v2.w));
                fma2(hacc[12], f2, pack2(v3.x, v3.x));
                fma2(hacc[13], f2, pack2(v3.y, v3.y));
                fma2(hacc[14], f2, pack2(v3.z, v3.z));
            }
            // transpose-store into s_h[jc][q]
            #pragma unroll
            for (int j = 0; j < KS_; ++j) {
                const float2 v = unpack2(hacc[j]);
                const int row = j * CIN + 2 * lane;
                s_h[row       * HSTR + q] = v.x;
                s_h[(row + 1) * HSTR + q] = v.y;
            }
        }
        __syncwarp();   // stg reused by next qq
    }
    __syncthreads();

    // ============ Stage C: warp = jc split, lane = 4 consecutive o, all 16 q =====
    {
        const int jc0 = wid * JCS;
        const float* wp = W + (size_t)jc0 * COUT + lane * 4;
        const float* hp = s_h + jc0 * HSTR;

        ull acc[4][8];
        #pragma unroll
        for (int oo = 0; oo < 4; ++oo)
            #pragma unroll
            for (int p = 0; p < 8; ++p) acc[oo][p] = 0ull;

        #pragma unroll 2
        for (int t = 0; t < JCS; ++t) {
            const float4 w4 = *(const float4*)(wp + (size_t)t * COUT);
            const longlong2* h2 = (const longlong2*)(hp + t * HSTR);
            const longlong2 ha = h2[0];
            const longlong2 hb = h2[1];
            const longlong2 hc = h2[2];
            const longlong2 hd = h2[3];
            const ull h[8] = { (ull)ha.x, (ull)ha.y, (ull)hb.x, (ull)hb.y,
                               (ull)hc.x, (ull)hc.y, (ull)hd.x, (ull)hd.y };
            const ull wx = pack2(w4.x, w4.x);
            const ull wy = pack2(w4.y, w4.y);
            const ull wz = pack2(w4.z, w4.z);
            const ull ww = pack2(w4.w, w4.w);
            #pragma unroll
            for (int p = 0; p < 8; ++p) {
                fma2(acc[0][p], h[p], wx);
                fma2(acc[1][p], h[p], wy);
                fma2(acc[2][p], h[p], wz);
                fma2(acc[3][p], h[p], ww);
            }
        }

        __syncthreads();   // s_h fully consumed; reuse as s_red

        // partials: s_red[split][o][RSTR]
        float* s_red = smem;
        float* basep = s_red + (size_t)(wid * COUT + lane * 4) * RSTR;
        #pragma unroll
        for (int oo = 0; oo < 4; ++oo)
            #pragma unroll
            for (int p = 0; p < 8; ++p)
                *(ull*)(basep + oo * RSTR + 2 * p) = acc[oo][p];
        __syncthreads();

        // final: sum 8 splits + bias, write out
        const int o  = tid & 127;
        const int qh = tid >> 7;
        const float bv = bias[o];
        #pragma unroll
        for (int rr = 0; rr < 8; ++rr) {
            const int q = qh * 8 + rr;
            float s = bv;
            #pragma unroll
            for (int sp2 = 0; sp2 < SPLITS; ++sp2)
                s += s_red[(size_t)(sp2 * COUT + o) * RSTR + q];
            out[((size_t)(b * N_ + q0 + q)) * COUT + o] = s;
        }
    }
}

extern "C" void kernel_launch(void* const* d_in, const int* in_sizes, int n_in,
                              void* d_out, int out_size) {
    const float* qp   = (const float*)d_in[0];
    const float* sp   = (const float*)d_in[1];
    const float* sf   = (const float*)d_in[2];
    const int*   nidx = (const int*)  d_in[3];
    const float* kp   = (const float*)d_in[4];
    const float* W    = (const float*)d_in[5];
    const float* bias = (const float*)d_in[6];
    float* out = (float*)d_out;

    const int smem_bytes =
        (JC * HSTR + SPLITS * K_ * ISTR + QT * 3 + KS_ * 3 + 16)
        * (int)sizeof(float);

    static bool attr_set = false;
    if (!attr_set) {
        cudaFuncSetAttribute(kpconv_kernel,
                             cudaFuncAttributeMaxDynamicSharedMemorySize,
                             smem_bytes);
        attr_set = true;
    }

    const int grid = B_ * (N_ / QT);   // 2048 CTAs
    kpconv_kernel<<<grid, NTHREADS, smem_bytes>>>(qp, sp, sf, nidx, kp, W, bias, out);
}

// round 5
// speedup vs baseline: 2.5296x; 1.4199x over previous
#include <cuda_runtime.h>
#include <cuda_fp16.h>
#include <cstdint>

#define B_    2
#define N_    16384
#define M_    16384
#define K_    32
#define CIN   64
#define COUT  128
#define KS_   15
#define JC    960
#define QT    32              // queries per CTA
#define NTH   256
#define SH    968             // s_h row stride (halves)
#define SW    104             // s_w row stride (halves)
#define KC    96              // k per W chunk
#define NCHUNK 10
#define ISTR  16              // influence staging stride (floats)

typedef unsigned long long ull;
typedef uint32_t u32;

// ---------------- packed f32x2 helpers ----------------
__device__ __forceinline__ ull pack2(float lo, float hi) {
    ull r; asm("mov.b64 %0, {%1, %2};" : "=l"(r) : "f"(lo), "f"(hi)); return r;
}
__device__ __forceinline__ void fma2(ull& d, ull a, ull b) {
    asm("fma.rn.f32x2 %0, %1, %2, %3;" : "=l"(d) : "l"(a), "l"(b), "l"(d));
}
__device__ __forceinline__ float2 unpack2(ull v) {
    float2 f; asm("mov.b64 {%0, %1}, %2;" : "=f"(f.x), "=f"(f.y) : "l"(v)); return f;
}

// ---------------- HMMA m16n8k16 (baseline PTX, works on sm_103) ----------------
__device__ __forceinline__ void mma16816(float& d0, float& d1, float& d2, float& d3,
                                         u32 a0, u32 a1, u32 a2, u32 a3,
                                         u32 b0, u32 b1) {
    asm volatile(
        "mma.sync.aligned.m16n8k16.row.col.f32.f16.f16.f32 "
        "{%0,%1,%2,%3}, {%4,%5,%6,%7}, {%8,%9}, {%0,%1,%2,%3};"
        : "+f"(d0), "+f"(d1), "+f"(d2), "+f"(d3)
        : "r"(a0), "r"(a1), "r"(a2), "r"(a3), "r"(b0), "r"(b1));
}

// ---------------- global fp16 transposed weights: [o][jc] ----------------
__device__ __align__(16) __half g_Wt[COUT * JC];

__global__ void convert_w(const float* __restrict__ W) {
    const int t = blockIdx.x * blockDim.x + threadIdx.x;
    if (t >= COUT * JC) return;
    const int o  = t & 127;          // coalesced read of W[jc][o]
    const int jc = t >> 7;
    g_Wt[(size_t)o * JC + jc] = __float2half(W[(size_t)jc * COUT + o]);
}

// ---------------- smem layout (bytes) ----------------
#define SM_H    0                    // 32*968*2      = 61952
#define SM_W    61952                // 128*104*2     = 26624
#define SM_STG  88576                // 8*32*16*4     = 16384
#define SM_BIAS 104960               // 128*4         = 512
#define SM_QP   105472               // 32*3*4        = 384
#define SM_KP   105856               // 45*4          = 180
#define SMEM_TOTAL 106048

__global__ __launch_bounds__(NTH, 2)
void kpconv_main(const float* __restrict__ qp,
                 const float* __restrict__ sp,
                 const float* __restrict__ sf,
                 const int*   __restrict__ nidx,
                 const float* __restrict__ kp,
                 const float* __restrict__ bias,
                 float*       __restrict__ out)
{
    extern __shared__ char smem[];
    const int tid  = threadIdx.x;
    const int wid  = tid >> 5;
    const int lane = tid & 31;
    const int b    = blockIdx.x >> 9;            // 512 tiles per batch
    const int q0   = (blockIdx.x & 511) * QT;

    float* s_qp   = (float*)(smem + SM_QP);
    float* s_kp   = (float*)(smem + SM_KP);
    float* s_bias = (float*)(smem + SM_BIAS);

    if (tid < KS_ * 3) s_kp[tid] = kp[tid];
    if (tid < COUT)    s_bias[tid] = bias[tid];
    if (tid < QT * 3)  s_qp[tid] = qp[(size_t)(b * N_ + q0) * 3 + tid];
    __syncthreads();

    // ============ fused Stage A (influences) + Stage B (h -> fp16 smem) ========
    {
        float* stg = (float*)(smem + SM_STG) + wid * 32 * ISTR;

        #pragma unroll 1
        for (int qi = 0; qi < 4; ++qi) {
            const int q = wid * 4 + qi;

            // --- Stage A: lane = neighbor k ---
            const int myidx = nidx[((size_t)(b * N_ + q0 + q)) * K_ + lane];
            {
                const float* p = sp + (size_t)(b * M_ + myidx) * 3;
                const float rx = p[0] - s_qp[q * 3 + 0];
                const float ry = p[1] - s_qp[q * 3 + 1];
                const float rz = p[2] - s_qp[q * 3 + 2];
                float e[KS_];
                float sum = 0.f;
                #pragma unroll
                for (int j = 0; j < KS_; ++j) {
                    const float dx = rx - s_kp[j * 3 + 0];
                    const float dy = ry - s_kp[j * 3 + 1];
                    const float dz = rz - s_kp[j * 3 + 2];
                    const float d2 = dx * dx + dy * dy + dz * dz;
                    e[j] = __expf(-200.0f * d2);        // sigma = 0.05
                    sum += e[j];
                }
                const float inv = 1.0f / (sum + 1e-6f);
                #pragma unroll
                for (int j = 0; j < KS_; ++j)
                    stg[lane * ISTR + j] = e[j] * inv;
                stg[lane * ISTR + 15] = 0.0f;           // pad for float4 read
            }
            __syncwarp();

            // --- Stage B: lane = channel pair (c = 2*lane, 2*lane+1) ---
            {
                ull hacc[KS_];
                #pragma unroll
                for (int j = 0; j < KS_; ++j) hacc[j] = 0ull;

                const float* sfb = sf + (size_t)b * M_ * CIN + 2 * lane;
                #pragma unroll 4
                for (int k = 0; k < K_; ++k) {
                    const int idx = __shfl_sync(0xffffffffu, myidx, k);
                    const ull f2 = *(const ull*)(sfb + (size_t)idx * CIN);
                    const float4* ip = (const float4*)(stg + k * ISTR);
                    const float4 v0 = ip[0];
                    const float4 v1 = ip[1];
                    const float4 v2 = ip[2];
                    const float4 v3 = ip[3];
                    fma2(hacc[0],  f2, pack2(v0.x, v0.x));
                    fma2(hacc[1],  f2, pack2(v0.y, v0.y));
                    fma2(hacc[2],  f2, pack2(v0.z, v0.z));
                    fma2(hacc[3],  f2, pack2(v0.w, v0.w));
                    fma2(hacc[4],  f2, pack2(v1.x, v1.x));
                    fma2(hacc[5],  f2, pack2(v1.y, v1.y));
                    fma2(hacc[6],  f2, pack2(v1.z, v1.z));
                    fma2(hacc[7],  f2, pack2(v1.w, v1.w));
                    fma2(hacc[8],  f2, pack2(v2.x, v2.x));
                    fma2(hacc[9],  f2, pack2(v2.y, v2.y));
                    fma2(hacc[10], f2, pack2(v2.z, v2.z));
                    fma2(hacc[11], f2, pack2(v2.w, v2.w));
                    fma2(hacc[12], f2, pack2(v3.x, v3.x));
                    fma2(hacc[13], f2, pack2(v3.y, v3.y));
                    fma2(hacc[14], f2, pack2(v3.z, v3.z));
                }
                // store h fp16: s_h[q][jc], jc = j*64 + 2*lane (+1)
                __half* hrow = (__half*)(smem + SM_H) + (size_t)q * SH + 2 * lane;
                #pragma unroll
                for (int j = 0; j < KS_; ++j) {
                    const float2 v = unpack2(hacc[j]);
                    *(__half2*)(hrow + j * 64) = __floats2half2_rn(v.x, v.y);
                }
            }
            __syncwarp();   // stg reused by next qi
        }
    }
    __syncthreads();

    // ============ Stage C: tensor-core GEMM  out[32q][128o] = h * W^T ==========
    {
        const int gid = lane >> 2;          // 0..7
        const int tig = lane & 3;           // 0..3
        const int q0w = (wid >> 2) * 16;    // warp q tile
        const int o0  = (wid & 3) * 32;     // warp o tile

        float acc[4][4];
        #pragma unroll
        for (int nt = 0; nt < 4; ++nt)
            #pragma unroll
            for (int i = 0; i < 4; ++i) acc[nt][i] = 0.f;

        const char* h_a = smem + SM_H
                        + ((size_t)(q0w + gid) * SH + tig * 2) * 2;
        const char* h_b = smem + SM_W
                        + ((size_t)(o0 + gid) * SW + tig * 2) * 2;

        #pragma unroll 1
        for (int c = 0; c < NCHUNK; ++c) {
            if (c) __syncthreads();         // previous chunk fully consumed

            // cooperative load of W chunk: s_w[o][0..95] <- g_Wt[o][c*96 ...]
            {
                const int o    = tid >> 1;
                const int part = tid & 1;
                const uint4* src = (const uint4*)((const char*)g_Wt
                                   + (size_t)o * (JC * 2) + c * (KC * 2) + part * 96);
                uint4* dst = (uint4*)(smem + SM_W + o * (SW * 2) + part * 96);
                #pragma unroll
                for (int i = 0; i < 6; ++i) dst[i] = src[i];
            }
            __syncthreads();

            #pragma unroll
            for (int ks = 0; ks < 6; ++ks) {
                const int koffA = (c * KC + ks * 16) * 2;   // bytes into A row
                const int koffB = (ks * 16) * 2;            // bytes into B row
                const u32 a0 = *(const u32*)(h_a + koffA);
                const u32 a1 = *(const u32*)(h_a + koffA + 8 * SH * 2);
                const u32 a2 = *(const u32*)(h_a + koffA + 16);
                const u32 a3 = *(const u32*)(h_a + koffA + 8 * SH * 2 + 16);
                #pragma unroll
                for (int nt = 0; nt < 4; ++nt) {
                    const u32 b0 = *(const u32*)(h_b + koffB + nt * 8 * SW * 2);
                    const u32 b1 = *(const u32*)(h_b + koffB + nt * 8 * SW * 2 + 16);
                    mma16816(acc[nt][0], acc[nt][1], acc[nt][2], acc[nt][3],
                             a0, a1, a2, a3, b0, b1);
                }
            }
        }

        // epilogue: bias + store
        const int qA = q0 + q0w + gid;
        #pragma unroll
        for (int nt = 0; nt < 4; ++nt) {
            const int o = o0 + nt * 8 + tig * 2;
            const float2 bv = *(const float2*)(s_bias + o);
            float2 r0, r1;
            r0.x = acc[nt][0] + bv.x;  r0.y = acc[nt][1] + bv.y;
            r1.x = acc[nt][2] + bv.x;  r1.y = acc[nt][3] + bv.y;
            *(float2*)(out + ((size_t)(b * N_ + qA))     * COUT + o) = r0;
            *(float2*)(out + ((size_t)(b * N_ + qA + 8)) * COUT + o) = r1;
        }
    }
}

// ---------------- launch ----------------
extern "C" void kernel_launch(void* const* d_in, const int* in_sizes, int n_in,
                              void* d_out, int out_size) {
    const float* qp   = (const float*)d_in[0];
    const float* sp   = (const float*)d_in[1];
    const float* sf   = (const float*)d_in[2];
    const int*   nidx = (const int*)  d_in[3];
    const float* kp   = (const float*)d_in[4];
    const float* W    = (const float*)d_in[5];
    const float* bias = (const float*)d_in[6];
    float* out = (float*)d_out;

    static bool attr_set = false;
    if (!attr_set) {
        cudaFuncSetAttribute(kpconv_main,
                             cudaFuncAttributeMaxDynamicSharedMemorySize,
                             SMEM_TOTAL);
        attr_set = true;
    }

    convert_w<<<(COUT * JC + NTH - 1) / NTH, NTH>>>(W);
    kpconv_main<<<B_ * (N_ / QT), NTH, SMEM_TOTAL>>>(qp, sp, sf, nidx, kp, bias, out);
}

// round 6
// speedup vs baseline: 2.9230x; 1.1555x over previous
#include <cuda_runtime.h>
#include <cuda_fp16.h>
#include <cstdint>

#define B_    2
#define N_    16384
#define M_    16384
#define K_    32
#define CIN   64
#define COUT  128
#define KS_   15
#define JC    960
#define QT    32              // queries per CTA
#define NTH   256
#define SH    968             // s_h row stride (halves)
#define SW    104             // s_w row stride (halves)
#define KC    96              // k per W chunk
#define NCHUNK 10
#define ISTR  16              // influence staging stride (floats)

typedef unsigned long long ull;
typedef uint32_t u32;

// ---------------- packed f32x2 helpers ----------------
__device__ __forceinline__ ull pack2(float lo, float hi) {
    ull r; asm("mov.b64 %0, {%1, %2};" : "=l"(r) : "f"(lo), "f"(hi)); return r;
}
__device__ __forceinline__ void fma2(ull& d, ull a, ull b) {
    asm("fma.rn.f32x2 %0, %1, %2, %3;" : "=l"(d) : "l"(a), "l"(b), "l"(d));
}
__device__ __forceinline__ float2 unpack2(ull v) {
    float2 f; asm("mov.b64 {%0, %1}, %2;" : "=f"(f.x), "=f"(f.y) : "l"(v)); return f;
}

// ---------------- HMMA m16n8k16 + LDSM (baseline PTX, sm_103-safe) ------------
__device__ __forceinline__ void mma16816(float& d0, float& d1, float& d2, float& d3,
                                         u32 a0, u32 a1, u32 a2, u32 a3,
                                         u32 b0, u32 b1) {
    asm volatile(
        "mma.sync.aligned.m16n8k16.row.col.f32.f16.f16.f32 "
        "{%0,%1,%2,%3}, {%4,%5,%6,%7}, {%8,%9}, {%0,%1,%2,%3};"
        : "+f"(d0), "+f"(d1), "+f"(d2), "+f"(d3)
        : "r"(a0), "r"(a1), "r"(a2), "r"(a3), "r"(b0), "r"(b1));
}
__device__ __forceinline__ void ldsm_x4(u32& r0, u32& r1, u32& r2, u32& r3,
                                        u32 addr) {
    asm volatile("ldmatrix.sync.aligned.m8n8.x4.shared.b16 {%0,%1,%2,%3}, [%4];"
                 : "=r"(r0), "=r"(r1), "=r"(r2), "=r"(r3) : "r"(addr));
}
__device__ __forceinline__ u32 smem_u32(const void* p) {
    u32 a;
    asm("{ .reg .u64 t; cvta.to.shared.u64 t, %1; cvt.u32.u64 %0, t; }"
        : "=r"(a) : "l"(p));
    return a;
}

// ---------------- global fp16 transposed weights: [o][jc] ----------------
__device__ __align__(16) __half g_Wt[COUT * JC];

__global__ void convert_w(const float* __restrict__ W) {
    const int t = blockIdx.x * blockDim.x + threadIdx.x;
    if (t >= COUT * JC) return;
    const int o  = t & 127;          // coalesced read of W[jc][o]
    const int jc = t >> 7;
    g_Wt[(size_t)o * JC + jc] = __float2half(W[(size_t)jc * COUT + o]);
}

// ---------------- smem layout (bytes) ----------------
#define SM_H    0                    // 32*968*2      = 61952
#define SM_W    61952                // 128*104*2     = 26624
#define SM_STG  88576                // 8*32*16*4     = 16384
#define SM_BIAS 104960               // 128*4         = 512
#define SM_QP   105472               // 32*3*4        = 384
#define SM_KP   105856               // 45*4          = 180
#define SMEM_TOTAL 106048

__global__ __launch_bounds__(NTH, 2)
void kpconv_main(const float* __restrict__ qp,
                 const float* __restrict__ sp,
                 const float* __restrict__ sf,
                 const int*   __restrict__ nidx,
                 const float* __restrict__ kp,
                 const float* __restrict__ bias,
                 float*       __restrict__ out)
{
    extern __shared__ char smem[];
    const int tid  = threadIdx.x;
    const int wid  = tid >> 5;
    const int lane = tid & 31;
    const int b    = blockIdx.x >> 9;            // 512 tiles per batch
    const int q0   = (blockIdx.x & 511) * QT;

    float* s_qp   = (float*)(smem + SM_QP);
    float* s_kp   = (float*)(smem + SM_KP);
    float* s_bias = (float*)(smem + SM_BIAS);

    if (tid < KS_ * 3) s_kp[tid] = kp[tid];
    if (tid < COUT)    s_bias[tid] = bias[tid];
    if (tid < QT * 3)  s_qp[tid] = qp[(size_t)(b * N_ + q0) * 3 + tid];
    __syncthreads();

    // ============ fused Stage A (influences) + Stage B (h -> fp16 smem) ========
    {
        float* stg = (float*)(smem + SM_STG) + wid * 32 * ISTR;

        #pragma unroll 1
        for (int qi = 0; qi < 4; ++qi) {
            const int q = wid * 4 + qi;

            // --- Stage A: lane = neighbor k ---
            const int myidx = nidx[((size_t)(b * N_ + q0 + q)) * K_ + lane];
            {
                const float* p = sp + (size_t)(b * M_ + myidx) * 3;
                const float rx = p[0] - s_qp[q * 3 + 0];
                const float ry = p[1] - s_qp[q * 3 + 1];
                const float rz = p[2] - s_qp[q * 3 + 2];
                float e[KS_];
                float sum = 0.f;
                #pragma unroll
                for (int j = 0; j < KS_; ++j) {
                    const float dx = rx - s_kp[j * 3 + 0];
                    const float dy = ry - s_kp[j * 3 + 1];
                    const float dz = rz - s_kp[j * 3 + 2];
                    const float d2 = dx * dx + dy * dy + dz * dz;
                    e[j] = __expf(-200.0f * d2);        // sigma = 0.05
                    sum += e[j];
                }
                const float inv = 1.0f / (sum + 1e-6f);
                #pragma unroll
                for (int j = 0; j < KS_; ++j)
                    stg[lane * ISTR + j] = e[j] * inv;
                stg[lane * ISTR + 15] = 0.0f;           // pad for float4 read
            }
            __syncwarp();

            // --- Stage B: lane = channel pair (c = 2*lane, 2*lane+1) ---
            {
                ull hacc[KS_];
                #pragma unroll
                for (int j = 0; j < KS_; ++j) hacc[j] = 0ull;

                const float* sfb = sf + (size_t)b * M_ * CIN + 2 * lane;
                #pragma unroll 4
                for (int k = 0; k < K_; ++k) {
                    const int idx = __shfl_sync(0xffffffffu, myidx, k);
                    const ull f2 = *(const ull*)(sfb + (size_t)idx * CIN);
                    const float4* ip = (const float4*)(stg + k * ISTR);
                    const float4 v0 = ip[0];
                    const float4 v1 = ip[1];
                    const float4 v2 = ip[2];
                    const float4 v3 = ip[3];
                    fma2(hacc[0],  f2, pack2(v0.x, v0.x));
                    fma2(hacc[1],  f2, pack2(v0.y, v0.y));
                    fma2(hacc[2],  f2, pack2(v0.z, v0.z));
                    fma2(hacc[3],  f2, pack2(v0.w, v0.w));
                    fma2(hacc[4],  f2, pack2(v1.x, v1.x));
                    fma2(hacc[5],  f2, pack2(v1.y, v1.y));
                    fma2(hacc[6],  f2, pack2(v1.z, v1.z));
                    fma2(hacc[7],  f2, pack2(v1.w, v1.w));
                    fma2(hacc[8],  f2, pack2(v2.x, v2.x));
                    fma2(hacc[9],  f2, pack2(v2.y, v2.y));
                    fma2(hacc[10], f2, pack2(v2.z, v2.z));
                    fma2(hacc[11], f2, pack2(v2.w, v2.w));
                    fma2(hacc[12], f2, pack2(v3.x, v3.x));
                    fma2(hacc[13], f2, pack2(v3.y, v3.y));
                    fma2(hacc[14], f2, pack2(v3.z, v3.z));
                }
                // store h fp16: s_h[q][jc], jc = j*64 + 2*lane (+1)
                __half* hrow = (__half*)(smem + SM_H) + (size_t)q * SH + 2 * lane;
                #pragma unroll
                for (int j = 0; j < KS_; ++j) {
                    const float2 v = unpack2(hacc[j]);
                    *(__half2*)(hrow + j * 64) = __floats2half2_rn(v.x, v.y);
                }
            }
            __syncwarp();   // stg reused by next qi
        }
    }

    // ---- prefetch W chunk 0 while stage B of other warps drains ----
    const int    wo    = tid >> 1;
    const int    wpart = tid & 1;
    const char*  wsrc  = (const char*)g_Wt + (size_t)wo * (JC * 2) + wpart * 96;
    uint4*       wdst  = (uint4*)(smem + SM_W + wo * (SW * 2) + wpart * 96);

    uint4 pf[6];
    {
        const uint4* s = (const uint4*)wsrc;
        #pragma unroll
        for (int i = 0; i < 6; ++i) pf[i] = s[i];
    }
    __syncthreads();

    // ============ Stage C: tensor-core GEMM  out[32q][128o] = h * W^T ==========
    {
        const int q0w = (wid >> 2) * 16;    // warp q tile
        const int o0  = (wid & 3) * 32;     // warp o tile
        const int r   = lane & 7;
        const int g   = lane >> 3;

        const u32 sbase = smem_u32(smem);
        // A x4: m0=(row,k0) m1=(row+8,k0) m2=(row,k8) m3=(row+8,k8)
        const u32 a_addr0 = sbase + SM_H
                          + ((u32)(q0w + r + (g & 1) * 8) * SH + (g >> 1) * 8) * 2;
        // B x4: m0=(o,k0) m1=(o,k8) m2=(o+8,k0) m3=(o+8,k8)
        const u32 b_addr0 = sbase + SM_W
                          + ((u32)(o0 + r + (g >> 1) * 8) * SW + (g & 1) * 8) * 2;
        const u32 b_addr1 = b_addr0 + 16 * SW * 2;

        float acc[4][4];
        #pragma unroll
        for (int nt = 0; nt < 4; ++nt)
            #pragma unroll
            for (int i = 0; i < 4; ++i) acc[nt][i] = 0.f;

        #pragma unroll 1
        for (int c = 0; c < NCHUNK; ++c) {
            // publish prefetched chunk c
            #pragma unroll
            for (int i = 0; i < 6; ++i) wdst[i] = pf[i];
            __syncthreads();

            // prefetch chunk c+1 (overlaps MMA below)
            if (c + 1 < NCHUNK) {
                const uint4* s = (const uint4*)(wsrc + (size_t)(c + 1) * (KC * 2));
                #pragma unroll
                for (int i = 0; i < 6; ++i) pf[i] = s[i];
            }

            const u32 a_c = a_addr0 + (u32)(c * KC) * 2;
            #pragma unroll
            for (int ks = 0; ks < 6; ++ks) {
                u32 a0, a1, a2, a3, b0, b1, b2, b3, b4, b5, b6, b7;
                ldsm_x4(a0, a1, a2, a3, a_c + ks * 32);
                ldsm_x4(b0, b1, b2, b3, b_addr0 + ks * 32);
                ldsm_x4(b4, b5, b6, b7, b_addr1 + ks * 32);
                mma16816(acc[0][0], acc[0][1], acc[0][2], acc[0][3],
                         a0, a1, a2, a3, b0, b1);
                mma16816(acc[1][0], acc[1][1], acc[1][2], acc[1][3],
                         a0, a1, a2, a3, b2, b3);
                mma16816(acc[2][0], acc[2][1], acc[2][2], acc[2][3],
                         a0, a1, a2, a3, b4, b5);
                mma16816(acc[3][0], acc[3][1], acc[3][2], acc[3][3],
                         a0, a1, a2, a3, b6, b7);
            }
            __syncthreads();    // chunk c fully consumed before overwrite
        }

        // epilogue: bias + store
        const int gid = lane >> 2;
        const int tig = lane & 3;
        const int qA = q0 + q0w + gid;
        #pragma unroll
        for (int nt = 0; nt < 4; ++nt) {
            const int o = o0 + nt * 8 + tig * 2;
            const float2 bv = *(const float2*)(s_bias + o);
            float2 r0, r1;
            r0.x = acc[nt][0] + bv.x;  r0.y = acc[nt][1] + bv.y;
            r1.x = acc[nt][2] + bv.x;  r1.y = acc[nt][3] + bv.y;
            *(float2*)(out + ((size_t)(b * N_ + qA))     * COUT + o) = r0;
            *(float2*)(out + ((size_t)(b * N_ + qA + 8)) * COUT + o) = r1;
        }
    }
}

// ---------------- launch ----------------
extern "C" void kernel_launch(void* const* d_in, const int* in_sizes, int n_in,
                              void* d_out, int out_size) {
    const float* qp   = (const float*)d_in[0];
    const float* sp   = (const float*)d_in[1];
    const float* sf   = (const float*)d_in[2];
    const int*   nidx = (const int*)  d_in[3];
    const float* kp   = (const float*)d_in[4];
    const float* W    = (const float*)d_in[5];
    const float* bias = (const float*)d_in[6];
    float* out = (float*)d_out;

    static bool attr_set = false;
    if (!attr_set) {
        cudaFuncSetAttribute(kpconv_main,
                             cudaFuncAttributeMaxDynamicSharedMemorySize,
                             SMEM_TOTAL);
        attr_set = true;
    }

    convert_w<<<(COUT * JC + NTH - 1) / NTH, NTH>>>(W);
    kpconv_main<<<B_ * (N_ / QT), NTH, SMEM_TOTAL>>>(qp, sp, sf, nidx, kp, bias, out);
}

// round 7
// speedup vs baseline: 5.3465x; 1.8291x over previous
#include <cuda_runtime.h>
#include <cuda_fp16.h>
#include <cstdint>

#define B_    2
#define N_    16384
#define M_    16384
#define K_    32
#define CIN   64
#define COUT  128
#define KS_   15
#define JC    960
#define QT    32
#define NTH   256
#define SH    968            // s_h row stride (halves); rows spread 16B apart mod 128
#define FSTR  72             // F-buf row stride (halves) = 144B -> ldsm.trans conflict-free
#define ISTRH 40             // I-buf row stride (halves) = 80B  -> ldsm conflict-free

typedef unsigned long long ull;
typedef uint32_t u32;

// ---------------- HMMA m16n8k16 + LDSM (baseline PTX, sm_103-safe) ------------
__device__ __forceinline__ void mma16816(float& d0, float& d1, float& d2, float& d3,
                                         u32 a0, u32 a1, u32 a2, u32 a3,
                                         u32 b0, u32 b1) {
    asm volatile(
        "mma.sync.aligned.m16n8k16.row.col.f32.f16.f16.f32 "
        "{%0,%1,%2,%3}, {%4,%5,%6,%7}, {%8,%9}, {%0,%1,%2,%3};"
        : "+f"(d0), "+f"(d1), "+f"(d2), "+f"(d3)
        : "r"(a0), "r"(a1), "r"(a2), "r"(a3), "r"(b0), "r"(b1));
}
__device__ __forceinline__ void ldsm_x4(u32& r0, u32& r1, u32& r2, u32& r3,
                                        u32 addr) {
    asm volatile("ldmatrix.sync.aligned.m8n8.x4.shared.b16 {%0,%1,%2,%3}, [%4];"
                 : "=r"(r0), "=r"(r1), "=r"(r2), "=r"(r3) : "r"(addr));
}
__device__ __forceinline__ void ldsm_x4_t(u32& r0, u32& r1, u32& r2, u32& r3,
                                          u32 addr) {
    asm volatile("ldmatrix.sync.aligned.m8n8.x4.trans.shared.b16 {%0,%1,%2,%3}, [%4];"
                 : "=r"(r0), "=r"(r1), "=r"(r2), "=r"(r3) : "r"(addr));
}
__device__ __forceinline__ u32 smem_u32(const void* p) {
    u32 a;
    asm("{ .reg .u64 t; cvta.to.shared.u64 t, %1; cvt.u32.u64 %0, t; }"
        : "=r"(a) : "l"(p));
    return a;
}

// ---------------- W pre-packed into m16n8k16 B-fragment layout ----------------
// jc' permutation: col' = g*30 + 2*j + u  with  g = (c>>3)*4 + ((c&7)>>1),
//                  u = c&1,  j = kernel point.   (960 columns total)
// g_Wfrag layout: [ks 0..59][ot 0..3][lane 0..31][nt 0..3][b0,b1] (u32 each)
__device__ __align__(16) u32 g_Wfrag[60 * 4 * 32 * 8];

__global__ void convert_w(const float* __restrict__ W) {
    const int t = blockIdx.x * blockDim.x + threadIdx.x;
    if (t >= 60 * 4 * 32 * 4) return;
    const int nt   = t & 3;
    const int lane = (t >> 2) & 31;
    const int ot   = (t >> 7) & 3;
    const int ks   = t >> 9;
    const int o    = ot * 32 + nt * 8 + (lane >> 2);

    u32 b[2];
    #pragma unroll
    for (int reg = 0; reg < 2; ++reg) {
        __half hh[2];
        #pragma unroll
        for (int u = 0; u < 2; ++u) {
            const int jcp = ks * 16 + reg * 8 + (lane & 3) * 2 + u;
            const int g   = jcp / 30;
            const int rem = jcp - g * 30;
            const int j   = rem >> 1;
            const int uu  = rem & 1;
            const int c   = (g >> 2) * 8 + (g & 3) * 2 + uu;
            hh[u] = __float2half_rn(W[(size_t)(j * 64 + c) * COUT + o]);
        }
        __half2 p = __halves2half2(hh[0], hh[1]);
        b[reg] = *reinterpret_cast<u32*>(&p);
    }
    u32* dst = g_Wfrag + ((size_t)((ks * 4 + ot) * 32 + lane)) * 8 + nt * 2;
    dst[0] = b[0];
    dst[1] = b[1];
}

// ---------------- smem layout (bytes) ----------------
#define SM_H    0                    // 32 * 968 * 2          = 61952
#define SM_F    61952                // 8 * 32 * 144          = 36864
#define SM_I    98816                // 8 * 16 * 80           = 10240
#define SM_BIAS 109056               // 512
#define SM_QP   109568               // 384
#define SM_KP   109952               // 192
#define SMEM_TOTAL 110208

__global__ __launch_bounds__(NTH, 2)
void kpconv_main(const float* __restrict__ qp,
                 const float* __restrict__ sp,
                 const float* __restrict__ sf,
                 const int*   __restrict__ nidx,
                 const float* __restrict__ kp,
                 const float* __restrict__ bias,
                 float*       __restrict__ out)
{
    extern __shared__ char smem[];
    const int tid  = threadIdx.x;
    const int wid  = tid >> 5;
    const int lane = tid & 31;
    const int b    = blockIdx.x >> 9;            // 512 tiles per batch
    const int q0   = (blockIdx.x & 511) * QT;

    float* s_qp   = (float*)(smem + SM_QP);
    float* s_kp   = (float*)(smem + SM_KP);
    float* s_bias = (float*)(smem + SM_BIAS);

    if (tid < KS_ * 3) s_kp[tid] = kp[tid];
    if (tid < COUT)    s_bias[tid] = bias[tid];
    if (tid < QT * 3)  s_qp[tid] = qp[(size_t)(b * N_ + q0) * 3 + tid];
    __syncthreads();

    const u32 sbase = smem_u32(smem);

    // ============ fused Stage A + Stage B (HMMA) : h -> s_h (permuted fp16) ====
    {
        __half* Fb = (__half*)(smem + SM_F) + wid * (32 * FSTR);
        __half* Ib = (__half*)(smem + SM_I) + wid * (16 * ISTRH);
        const u32 fb_u = sbase + SM_F + wid * (32 * FSTR * 2);
        const u32 ib_u = sbase + SM_I + wid * (16 * ISTRH * 2);

        Ib[15 * ISTRH + lane] = __float2half(0.0f);   // padded j=15 row

        #pragma unroll 1
        for (int qi = 0; qi < 4; ++qi) {
            const int q = wid * 4 + qi;
            const int myidx = nidx[((size_t)(b * N_ + q0 + q)) * K_ + lane];

            // --- Stage A: lane = neighbor k; write fp16 influences I[j][k] ---
            {
                const float* p = sp + (size_t)(b * M_ + myidx) * 3;
                const float rx = p[0] - s_qp[q * 3 + 0];
                const float ry = p[1] - s_qp[q * 3 + 1];
                const float rz = p[2] - s_qp[q * 3 + 2];
                float e[KS_];
                float sum = 0.f;
                #pragma unroll
                for (int j = 0; j < KS_; ++j) {
                    const float dx = rx - s_kp[j * 3 + 0];
                    const float dy = ry - s_kp[j * 3 + 1];
                    const float dz = rz - s_kp[j * 3 + 2];
                    const float d2 = dx * dx + dy * dy + dz * dz;
                    e[j] = __expf(-200.0f * d2);        // sigma = 0.05
                    sum += e[j];
                }
                const float inv = 1.0f / (sum + 1e-6f);
                #pragma unroll
                for (int j = 0; j < KS_; ++j)
                    Ib[j * ISTRH + lane] = __float2half_rn(e[j] * inv);
            }
            __syncwarp();

            // --- gather features F[k][c] fp16 (fp32 source, cvt in-flight) ---
            {
                const float* sfb = sf + (size_t)b * M_ * CIN + (lane & 15) * 4;
                const int ksub = lane >> 4;
                #pragma unroll 4
                for (int it = 0; it < 16; ++it) {
                    const int kk  = 2 * it + ksub;
                    const int idx = __shfl_sync(0xffffffffu, myidx, kk);
                    const float4 f4 = *(const float4*)(sfb + (size_t)idx * CIN);
                    __half2 h0 = __floats2half2_rn(f4.x, f4.y);
                    __half2 h1 = __floats2half2_rn(f4.z, f4.w);
                    const ull pkd = ((ull)*reinterpret_cast<u32*>(&h1) << 32)
                                  | (ull)*reinterpret_cast<u32*>(&h0);
                    *(ull*)(Fb + kk * FSTR + (lane & 15) * 4) = pkd;
                }
            }
            __syncwarp();

            // --- MMA: h[16j][64c] = I[16j][32k] * F[32k][64c] ---
            u32 aI[2][4];
            ldsm_x4(aI[0][0], aI[0][1], aI[0][2], aI[0][3],
                    ib_u + (lane & 15) * (ISTRH * 2) + (lane >> 4) * 16);
            ldsm_x4(aI[1][0], aI[1][1], aI[1][2], aI[1][3],
                    ib_u + (lane & 15) * (ISTRH * 2) + (lane >> 4) * 16 + 32);

            float acc[8][4];
            #pragma unroll
            for (int nt = 0; nt < 8; ++nt)
                #pragma unroll
                for (int i = 0; i < 4; ++i) acc[nt][i] = 0.f;

            #pragma unroll
            for (int cp = 0; cp < 4; ++cp) {
                #pragma unroll
                for (int k2 = 0; k2 < 2; ++k2) {
                    u32 b0, b1, b2, b3;
                    ldsm_x4_t(b0, b1, b2, b3,
                              fb_u + (u32)(k2 * 16 + (lane & 15)) * (FSTR * 2)
                                   + (u32)(cp * 16 + (lane >> 4) * 8) * 2);
                    mma16816(acc[cp*2][0], acc[cp*2][1], acc[cp*2][2], acc[cp*2][3],
                             aI[k2][0], aI[k2][1], aI[k2][2], aI[k2][3], b0, b1);
                    mma16816(acc[cp*2+1][0], acc[cp*2+1][1], acc[cp*2+1][2], acc[cp*2+1][3],
                             aI[k2][0], aI[k2][1], aI[k2][2], aI[k2][3], b2, b3);
                }
            }

            // --- writeback h (permuted columns, fp16) ---
            // thread (g = lane>>2 -> j, t = lane&3), col' byte = (nt*4+t)*60 + 4*j
            {
                char* hq = smem + SM_H + (size_t)q * (SH * 2);
                const int g = lane >> 2;
                const int t = lane & 3;
                #pragma unroll
                for (int nt = 0; nt < 8; ++nt) {
                    const int off = (nt * 4 + t) * 60 + g * 4;
                    *(__half2*)(hq + off) =
                        __floats2half2_rn(acc[nt][0], acc[nt][1]);
                    if (g != 7)
                        *(__half2*)(hq + off + 32) =
                            __floats2half2_rn(acc[nt][2], acc[nt][3]);
                }
            }
            __syncwarp();   // F/I buffers reused next qi
        }
    }
    __syncthreads();

    // ============ Stage C: out[32q][128o] = h * Wfrag (direct-LDG B frags) =====
    {
        const int ot  = wid & 3;
        const int q0w = (wid >> 2) * 16;
        const int o0  = ot * 32;

        const u32 a_addr = sbase + SM_H
                         + (u32)(q0w + (lane & 15)) * (SH * 2)
                         + (u32)(lane >> 4) * 16;
        const uint4* wf = reinterpret_cast<const uint4*>(g_Wfrag)
                        + ((size_t)ot * 32 + lane) * 2;

        float acc[4][4];
        #pragma unroll
        for (int nt = 0; nt < 4; ++nt)
            #pragma unroll
            for (int i = 0; i < 4; ++i) acc[nt][i] = 0.f;

        #pragma unroll 4
        for (int ks = 0; ks < 60; ++ks) {
            const uint4 w0 = wf[(size_t)ks * 256];
            const uint4 w1 = wf[(size_t)ks * 256 + 1];
            u32 a0, a1, a2, a3;
            ldsm_x4(a0, a1, a2, a3, a_addr + ks * 32);
            mma16816(acc[0][0], acc[0][1], acc[0][2], acc[0][3],
                     a0, a1, a2, a3, w0.x, w0.y);
            mma16816(acc[1][0], acc[1][1], acc[1][2], acc[1][3],
                     a0, a1, a2, a3, w0.z, w0.w);
            mma16816(acc[2][0], acc[2][1], acc[2][2], acc[2][3],
                     a0, a1, a2, a3, w1.x, w1.y);
            mma16816(acc[3][0], acc[3][1], acc[3][2], acc[3][3],
                     a0, a1, a2, a3, w1.z, w1.w);
        }

        // epilogue: bias + store
        const int gid = lane >> 2;
        const int tig = lane & 3;
        const int qA = q0 + q0w + gid;
        #pragma unroll
        for (int nt = 0; nt < 4; ++nt) {
            const int o = o0 + nt * 8 + tig * 2;
            const float2 bv = *(const float2*)(s_bias + o);
            float2 r0, r1;
            r0.x = acc[nt][0] + bv.x;  r0.y = acc[nt][1] + bv.y;
            r1.x = acc[nt][2] + bv.x;  r1.y = acc[nt][3] + bv.y;
            *(float2*)(out + ((size_t)(b * N_ + qA))     * COUT + o) = r0;
            *(float2*)(out + ((size_t)(b * N_ + qA + 8)) * COUT + o) = r1;
        }
    }
}

// ---------------- launch ----------------
extern "C" void kernel_launch(void* const* d_in, const int* in_sizes, int n_in,
                              void* d_out, int out_size) {
    const float* qp   = (const float*)d_in[0];
    const float* sp   = (const float*)d_in[1];
    const float* sf   = (const float*)d_in[2];
    const int*   nidx = (const int*)  d_in[3];
    const float* kp   = (const float*)d_in[4];
    const float* W    = (const float*)d_in[5];
    const float* bias = (const float*)d_in[6];
    float* out = (float*)d_out;

    static bool attr_set = false;
    if (!attr_set) {
        cudaFuncSetAttribute(kpconv_main,
                             cudaFuncAttributeMaxDynamicSharedMemorySize,
                             SMEM_TOTAL);
        attr_set = true;
    }

    convert_w<<<(60 * 4 * 32 * 4 + NTH - 1) / NTH, NTH>>>(W);
    kpconv_main<<<B_ * (N_ / QT), NTH, SMEM_TOTAL>>>(qp, sp, sf, nidx, kp, bias, out);
}

// round 8
// speedup vs baseline: 6.7008x; 1.2533x over previous
#include <cuda_runtime.h>
#include <cuda_fp16.h>
#include <cstdint>

#define B_    2
#define N_    16384
#define M_    16384
#define K_    32
#define CIN   64
#define COUT  128
#define KS_   15
#define JC    960
#define QT    32
#define NTH   256
#define SH    968            // s_h row stride (halves)
#define FSTR  72             // F-buf row stride (halves) = 144B -> ldsm.trans conflict-free
#define ISTRH 40             // I-buf row stride (halves) = 80B  -> ldsm conflict-free

typedef unsigned long long ull;
typedef uint32_t u32;

// ---------------- HMMA m16n8k16 + LDSM (baseline PTX, sm_103-safe) ------------
__device__ __forceinline__ void mma16816(float& d0, float& d1, float& d2, float& d3,
                                         u32 a0, u32 a1, u32 a2, u32 a3,
                                         u32 b0, u32 b1) {
    asm volatile(
        "mma.sync.aligned.m16n8k16.row.col.f32.f16.f16.f32 "
        "{%0,%1,%2,%3}, {%4,%5,%6,%7}, {%8,%9}, {%0,%1,%2,%3};"
        : "+f"(d0), "+f"(d1), "+f"(d2), "+f"(d3)
        : "r"(a0), "r"(a1), "r"(a2), "r"(a3), "r"(b0), "r"(b1));
}
__device__ __forceinline__ void ldsm_x4(u32& r0, u32& r1, u32& r2, u32& r3,
                                        u32 addr) {
    asm volatile("ldmatrix.sync.aligned.m8n8.x4.shared.b16 {%0,%1,%2,%3}, [%4];"
                 : "=r"(r0), "=r"(r1), "=r"(r2), "=r"(r3) : "r"(addr));
}
__device__ __forceinline__ void ldsm_x4_t(u32& r0, u32& r1, u32& r2, u32& r3,
                                          u32 addr) {
    asm volatile("ldmatrix.sync.aligned.m8n8.x4.trans.shared.b16 {%0,%1,%2,%3}, [%4];"
                 : "=r"(r0), "=r"(r1), "=r"(r2), "=r"(r3) : "r"(addr));
}
__device__ __forceinline__ u32 smem_u32(const void* p) {
    u32 a;
    asm("{ .reg .u64 t; cvta.to.shared.u64 t, %1; cvt.u32.u64 %0, t; }"
        : "=r"(a) : "l"(p));
    return a;
}

// ---------------- pre-packed global images ----------------
__device__ __align__(16) u32    g_Wfrag[60 * 4 * 32 * 8];   // W in B-frag layout
__device__ __align__(16) __half g_sf16[B_ * M_ * CIN];      // fp16 features (128B rows)
__device__ __align__(16) float4 g_sp4[B_ * M_];             // xyz0 positions

// jc' permutation: col' = g*30 + 2*j + u  with  g = (c>>3)*4 + ((c&7)>>1),
//                  u = c&1,  j = kernel point.   (960 columns total)
__global__ void convert_w(const float* __restrict__ W) {
    const int t = blockIdx.x * blockDim.x + threadIdx.x;
    if (t >= 60 * 4 * 32 * 4) return;
    const int nt   = t & 3;
    const int lane = (t >> 2) & 31;
    const int ot   = (t >> 7) & 3;
    const int ks   = t >> 9;
    const int o    = ot * 32 + nt * 8 + (lane >> 2);

    u32 b[2];
    #pragma unroll
    for (int reg = 0; reg < 2; ++reg) {
        __half hh[2];
        #pragma unroll
        for (int u = 0; u < 2; ++u) {
            const int jcp = ks * 16 + reg * 8 + (lane & 3) * 2 + u;
            const int g   = jcp / 30;
            const int rem = jcp - g * 30;
            const int j   = rem >> 1;
            const int uu  = rem & 1;
            const int c   = (g >> 2) * 8 + (g & 3) * 2 + uu;
            hh[u] = __float2half_rn(W[(size_t)(j * 64 + c) * COUT + o]);
        }
        __half2 p = __halves2half2(hh[0], hh[1]);
        b[reg] = *reinterpret_cast<u32*>(&p);
    }
    u32* dst = g_Wfrag + ((size_t)((ks * 4 + ot) * 32 + lane)) * 8 + nt * 2;
    dst[0] = b[0];
    dst[1] = b[1];
}

__global__ void convert_sf(const float* __restrict__ sf) {
    const int t = blockIdx.x * blockDim.x + threadIdx.x;   // B_*M_*8 threads
    if (t >= B_ * M_ * 8) return;
    const size_t base = (size_t)t * 8;
    const float4 f0 = *(const float4*)(sf + base);
    const float4 f1 = *(const float4*)(sf + base + 4);
    __half2 h0 = __floats2half2_rn(f0.x, f0.y);
    __half2 h1 = __floats2half2_rn(f0.z, f0.w);
    __half2 h2 = __floats2half2_rn(f1.x, f1.y);
    __half2 h3 = __floats2half2_rn(f1.z, f1.w);
    uint4 v;
    v.x = *reinterpret_cast<u32*>(&h0);
    v.y = *reinterpret_cast<u32*>(&h1);
    v.z = *reinterpret_cast<u32*>(&h2);
    v.w = *reinterpret_cast<u32*>(&h3);
    *(uint4*)(g_sf16 + base) = v;
}

__global__ void convert_sp(const float* __restrict__ sp) {
    const int t = blockIdx.x * blockDim.x + threadIdx.x;
    if (t >= B_ * M_) return;
    g_sp4[t] = make_float4(sp[3 * t], sp[3 * t + 1], sp[3 * t + 2], 0.f);
}

// ---------------- smem layout (bytes) ----------------
#define SM_H    0                    // 32 * 968 * 2          = 61952
#define SM_F    61952                // 8 * 32 * 144          = 36864  (reused for reduction)
#define SM_I    98816                // 8 * 16 * 80           = 10240
#define SM_BIAS 109056               // 512
#define SM_QP   109568               // 384
#define SM_KP   109952               // 192
#define SMEM_TOTAL 110208

__global__ __launch_bounds__(NTH, 2)
void kpconv_main(const float* __restrict__ qp,
                 const int*   __restrict__ nidx,
                 const float* __restrict__ kp,
                 const float* __restrict__ bias,
                 float*       __restrict__ out)
{
    extern __shared__ char smem[];
    const int tid  = threadIdx.x;
    const int wid  = tid >> 5;
    const int lane = tid & 31;
    const int b    = blockIdx.x >> 9;            // 512 tiles per batch
    const int q0   = (blockIdx.x & 511) * QT;

    float* s_qp   = (float*)(smem + SM_QP);
    float* s_kp   = (float*)(smem + SM_KP);
    float* s_bias = (float*)(smem + SM_BIAS);

    if (tid < KS_ * 3) s_kp[tid] = kp[tid];
    if (tid < COUT)    s_bias[tid] = bias[tid];
    if (tid < QT * 3)  s_qp[tid] = qp[(size_t)(b * N_ + q0) * 3 + tid];
    __syncthreads();

    const u32 sbase = smem_u32(smem);

    // ============ fused Stage A + Stage B (HMMA) : h -> s_h (permuted fp16) ====
    {
        __half* Fb = (__half*)(smem + SM_F) + wid * (32 * FSTR);
        __half* Ib = (__half*)(smem + SM_I) + wid * (16 * ISTRH);
        const u32 fb_u = sbase + SM_F + wid * (32 * FSTR * 2);
        const u32 ib_u = sbase + SM_I + wid * (16 * ISTRH * 2);

        Ib[15 * ISTRH + lane] = __float2half(0.0f);   // padded j=15 row

        #pragma unroll 1
        for (int qi = 0; qi < 4; ++qi) {
            const int q = wid * 4 + qi;
            const int myidx = nidx[((size_t)(b * N_ + q0 + q)) * K_ + lane];

            // --- Stage A: lane = neighbor k; write fp16 influences I[j][k] ---
            {
                const float4 p4 = g_sp4[(size_t)b * M_ + myidx];
                const float rx = p4.x - s_qp[q * 3 + 0];
                const float ry = p4.y - s_qp[q * 3 + 1];
                const float rz = p4.z - s_qp[q * 3 + 2];
                float e[KS_];
                float sum = 0.f;
                #pragma unroll
                for (int j = 0; j < KS_; ++j) {
                    const float dx = rx - s_kp[j * 3 + 0];
                    const float dy = ry - s_kp[j * 3 + 1];
                    const float dz = rz - s_kp[j * 3 + 2];
                    const float d2 = dx * dx + dy * dy + dz * dz;
                    e[j] = __expf(-200.0f * d2);        // sigma = 0.05
                    sum += e[j];
                }
                const float inv = 1.0f / (sum + 1e-6f);
                #pragma unroll
                for (int j = 0; j < KS_; ++j)
                    Ib[j * ISTRH + lane] = __float2half_rn(e[j] * inv);
            }
            __syncwarp();

            // --- gather fp16 features F[k][c]: pure 16B copies ---
            {
                const __half* sfb = g_sf16 + (size_t)b * M_ * CIN + (lane & 7) * 8;
                const int sub = lane >> 3;               // row within 4-group
                #pragma unroll 4
                for (int it = 0; it < 8; ++it) {
                    const int kk  = it * 4 + sub;
                    const int idx = __shfl_sync(0xffffffffu, myidx, kk);
                    const uint4 v = *(const uint4*)(sfb + (size_t)idx * CIN);
                    *(uint4*)(Fb + kk * FSTR + (lane & 7) * 8) = v;
                }
            }
            __syncwarp();

            // --- MMA: h[16j][64c] = I[16j][32k] * F[32k][64c] ---
            u32 aI[2][4];
            ldsm_x4(aI[0][0], aI[0][1], aI[0][2], aI[0][3],
                    ib_u + (lane & 15) * (ISTRH * 2) + (lane >> 4) * 16);
            ldsm_x4(aI[1][0], aI[1][1], aI[1][2], aI[1][3],
                    ib_u + (lane & 15) * (ISTRH * 2) + (lane >> 4) * 16 + 32);

            float acc[8][4];
            #pragma unroll
            for (int nt = 0; nt < 8; ++nt)
                #pragma unroll
                for (int i = 0; i < 4; ++i) acc[nt][i] = 0.f;

            #pragma unroll
            for (int cp = 0; cp < 4; ++cp) {
                #pragma unroll
                for (int k2 = 0; k2 < 2; ++k2) {
                    u32 b0, b1, b2, b3;
                    ldsm_x4_t(b0, b1, b2, b3,
                              fb_u + (u32)(k2 * 16 + (lane & 15)) * (FSTR * 2)
                                   + (u32)(cp * 16 + (lane >> 4) * 8) * 2);
                    mma16816(acc[cp*2][0], acc[cp*2][1], acc[cp*2][2], acc[cp*2][3],
                             aI[k2][0], aI[k2][1], aI[k2][2], aI[k2][3], b0, b1);
                    mma16816(acc[cp*2+1][0], acc[cp*2+1][1], acc[cp*2+1][2], acc[cp*2+1][3],
                             aI[k2][0], aI[k2][1], aI[k2][2], aI[k2][3], b2, b3);
                }
            }

            // --- writeback h (permuted columns, fp16) ---
            {
                char* hq = smem + SM_H + (size_t)q * (SH * 2);
                const int g = lane >> 2;
                const int t = lane & 3;
                #pragma unroll
                for (int nt = 0; nt < 8; ++nt) {
                    const int off = (nt * 4 + t) * 60 + g * 4;
                    *(__half2*)(hq + off) =
                        __floats2half2_rn(acc[nt][0], acc[nt][1]);
                    if (g != 7)
                        *(__half2*)(hq + off + 32) =
                            __floats2half2_rn(acc[nt][2], acc[nt][3]);
                }
            }
            __syncwarp();   // F/I buffers reused next qi
        }
    }
    __syncthreads();

    // ============ Stage C: split-K GEMM, warp = 32q x 32o x 30ks ===============
    {
        const int ot    = wid & 3;
        const int khalf = wid >> 2;          // 0: ks 0-29, 1: ks 30-59
        const int o0    = ot * 32;

        const u32 a0_addr = sbase + SM_H
                          + (u32)(lane & 15) * (SH * 2) + (u32)(lane >> 4) * 16;
        const u32 a1_addr = a0_addr + 16 * (SH * 2);
        const uint4* wf = reinterpret_cast<const uint4*>(g_Wfrag)
                        + ((size_t)ot * 32 + lane) * 2;

        float acc[2][4][4];
        #pragma unroll
        for (int qt = 0; qt < 2; ++qt)
            #pragma unroll
            for (int nt = 0; nt < 4; ++nt)
                #pragma unroll
                for (int i = 0; i < 4; ++i) acc[qt][nt][i] = 0.f;

        const int ksb = khalf * 30;
        #pragma unroll 3
        for (int ks = 0; ks < 30; ++ks) {
            const int gks = ksb + ks;
            const uint4 w0 = wf[(size_t)gks * 256];
            const uint4 w1 = wf[(size_t)gks * 256 + 1];
            u32 x0, x1, x2, x3, y0, y1, y2, y3;
            ldsm_x4(x0, x1, x2, x3, a0_addr + gks * 32);
            ldsm_x4(y0, y1, y2, y3, a1_addr + gks * 32);
            mma16816(acc[0][0][0], acc[0][0][1], acc[0][0][2], acc[0][0][3],
                     x0, x1, x2, x3, w0.x, w0.y);
            mma16816(acc[0][1][0], acc[0][1][1], acc[0][1][2], acc[0][1][3],
                     x0, x1, x2, x3, w0.z, w0.w);
            mma16816(acc[0][2][0], acc[0][2][1], acc[0][2][2], acc[0][2][3],
                     x0, x1, x2, x3, w1.x, w1.y);
            mma16816(acc[0][3][0], acc[0][3][1], acc[0][3][2], acc[0][3][3],
                     x0, x1, x2, x3, w1.z, w1.w);
            mma16816(acc[1][0][0], acc[1][0][1], acc[1][0][2], acc[1][0][3],
                     y0, y1, y2, y3, w0.x, w0.y);
            mma16816(acc[1][1][0], acc[1][1][1], acc[1][1][2], acc[1][1][3],
                     y0, y1, y2, y3, w0.z, w0.w);
            mma16816(acc[1][2][0], acc[1][2][1], acc[1][2][2], acc[1][2][3],
                     y0, y1, y2, y3, w1.x, w1.y);
            mma16816(acc[1][3][0], acc[1][3][1], acc[1][3][2], acc[1][3][3],
                     y0, y1, y2, y3, w1.z, w1.w);
        }

        __syncthreads();   // s_h consumed; F region reusable for reduction
        float* red = (float*)(smem + SM_F);   // [32 i][4 ot][32 lane]

        if (khalf == 1) {
            #pragma unroll
            for (int i = 0; i < 32; ++i)
                red[(i * 4 + ot) * 32 + lane] = acc[i >> 4][(i >> 2) & 3][i & 3];
        }
        __syncthreads();

        if (khalf == 0) {
            const int gid = lane >> 2;
            const int tig = lane & 3;
            #pragma unroll
            for (int qt = 0; qt < 2; ++qt) {
                const int qA = q0 + qt * 16 + gid;
                #pragma unroll
                for (int nt = 0; nt < 4; ++nt) {
                    const int o = o0 + nt * 8 + tig * 2;
                    const float2 bv = *(const float2*)(s_bias + o);
                    const int ib = qt * 16 + nt * 4;
                    float2 r0, r1;
                    r0.x = acc[qt][nt][0] + red[((ib + 0) * 4 + ot) * 32 + lane] + bv.x;
                    r0.y = acc[qt][nt][1] + red[((ib + 1) * 4 + ot) * 32 + lane] + bv.y;
                    r1.x = acc[qt][nt][2] + red[((ib + 2) * 4 + ot) * 32 + lane] + bv.x;
                    r1.y = acc[qt][nt][3] + red[((ib + 3) * 4 + ot) * 32 + lane] + bv.y;
                    *(float2*)(out + ((size_t)(b * N_ + qA))     * COUT + o) = r0;
                    *(float2*)(out + ((size_t)(b * N_ + qA + 8)) * COUT + o) = r1;
                }
            }
        }
    }
}

// ---------------- launch ----------------
extern "C" void kernel_launch(void* const* d_in, const int* in_sizes, int n_in,
                              void* d_out, int out_size) {
    const float* qp   = (const float*)d_in[0];
    const float* sp   = (const float*)d_in[1];
    const float* sf   = (const float*)d_in[2];
    const int*   nidx = (const int*)  d_in[3];
    const float* kp   = (const float*)d_in[4];
    const float* W    = (const float*)d_in[5];
    const float* bias = (const float*)d_in[6];
    float* out = (float*)d_out;

    static bool attr_set = false;
    if (!attr_set) {
        cudaFuncSetAttribute(kpconv_main,
                             cudaFuncAttributeMaxDynamicSharedMemorySize,
                             SMEM_TOTAL);
        attr_set = true;
    }

    convert_w <<<(60 * 4 * 32 * 4 + NTH - 1) / NTH, NTH>>>(W);
    convert_sf<<<(B_ * M_ * 8 + NTH - 1) / NTH, NTH>>>(sf);
    convert_sp<<<(B_ * M_ + NTH - 1) / NTH, NTH>>>(sp);
    kpconv_main<<<B_ * (N_ / QT), NTH, SMEM_TOTAL>>>(qp, nidx, kp, bias, out);
}